// round 12
// baseline (speedup 1.0000x reference)
#include <cuda_runtime.h>
#include <cstdint>

// Problem constants
#define B_   4
#define S_   2048
#define EMB_ 1024
#define H_   16
#define DH_  64
#define M_   (B_ * S_)          // 8192 rows

// Scratch (module-static device memory; no cudaMalloc anywhere)
__device__ float g_Q[B_ * H_ * S_ * DH_];   // [bh][s][d]  (tf32-rounded, Q pre-scaled)
__device__ float g_K[B_ * H_ * S_ * DH_];
__device__ float g_V[B_ * H_ * S_ * DH_];
__device__ float g_ctx[M_ * EMB_];          // [b*s][emb]  (tf32-rounded)
__device__ float g_xr[M_ * EMB_];           // tf32-rounded x
__device__ float g_Wr[4 * EMB_ * EMB_];     // tf32-rounded Wq,Wk,Wv,Wo

// ---------------------------------------------------------------------------
// Helpers
// ---------------------------------------------------------------------------
__device__ __forceinline__ uint32_t tf32r(float f) {
    uint32_t u;
    asm("cvt.rna.tf32.f32 %0, %1;" : "=r"(u) : "f"(f));
    return u;
}

__device__ __forceinline__ void mma_tf32(float* c, const uint32_t* a,
                                         uint32_t b0, uint32_t b1) {
    asm volatile(
        "mma.sync.aligned.m16n8k8.row.col.f32.tf32.tf32.f32 "
        "{%0,%1,%2,%3}, {%4,%5,%6,%7}, {%8,%9}, {%0,%1,%2,%3};"
        : "+f"(c[0]), "+f"(c[1]), "+f"(c[2]), "+f"(c[3])
        : "r"(a[0]), "r"(a[1]), "r"(a[2]), "r"(a[3]), "r"(b0), "r"(b1));
}

__device__ __forceinline__ uint32_t smemu32(const void* p) {
    uint32_t a;
    asm("{ .reg .u64 t; cvta.to.shared.u64 t, %1; cvt.u32.u64 %0, t; }"
        : "=r"(a) : "l"(p));
    return a;
}

__device__ __forceinline__ void cpasync16(uint32_t dst, const void* src) {
    asm volatile("cp.async.cg.shared.global [%0], [%1], 16;"
                 :: "r"(dst), "l"(src) : "memory");
}

// ---------------------------------------------------------------------------
// Prep kernel: round x and the four weight matrices to tf32 once.
// float4 granularity; grid covers x (2M float4) then 4 W (256K float4 each).
// ---------------------------------------------------------------------------
__global__ __launch_bounds__(256) void round_prep_kernel(
    const float* __restrict__ x,
    const float* __restrict__ Wq, const float* __restrict__ Wk,
    const float* __restrict__ Wv, const float* __restrict__ Wo)
{
    size_t i = (size_t)blockIdx.x * 256 + threadIdx.x;   // float4 index
    const float4* src;
    uint4* dst;
    size_t off;
    if (i < 2097152) {                                   // x: 8M floats
        src = (const float4*)x;
        dst = (uint4*)g_xr;
        off = i;
    } else {
        size_t j = i - 2097152;
        int t = (int)(j >> 18);                          // 262144 float4 per W
        off = j & 262143;
        const float* w = (t == 0) ? Wq : (t == 1) ? Wk : (t == 2) ? Wv : Wo;
        src = (const float4*)w;
        dst = (uint4*)(g_Wr + (size_t)t * (EMB_ * EMB_));
    }
    float4 v = src[off];
    uint4 u;
    u.x = tf32r(v.x); u.y = tf32r(v.y); u.z = tf32r(v.z); u.w = tf32r(v.w);
    dst[off] = u;
}

// ---------------------------------------------------------------------------
// tf32 mma.sync GEMM v2: cp.async 2-stage double-buffered pipeline.
// out[m,n] = sum_k A[m,k] * W[k,n] + bias[n]
// A and W must be pre-rounded to tf32 (raw bit copies into smem).
// CTA tile 128x128, BK=32, 256 threads = 8 warps (4m x 2n), warp tile 32x64.
// mode: 0 = oproj (row-major fp32 out), 1 = K/V (scatter + tf32 round),
//       2 = Q (scatter + *0.125 + tf32 round)
// Dynamic smem (u32): As[2][128][36] @0/4608, Bs[2][32][132] @9216/13440
// ---------------------------------------------------------------------------
#define GSM_AS1   4608
#define GSM_BS0   9216
#define GSM_BS1   13440
#define GSM_U32   17664
#define GSM_BYTES (GSM_U32 * 4)

__device__ __forceinline__ void gemm_mma_body(
    const float* __restrict__ A, const float* __restrict__ W,
    const float* __restrict__ bias, float* __restrict__ out, int mode)
{
    extern __shared__ uint32_t gsm[];
    const uint32_t sbase = smemu32(gsm);

    const int tid  = threadIdx.x;
    const int lane = tid & 31;
    const int wid  = tid >> 5;
    const int wm   = wid & 3;
    const int wn   = wid >> 2;
    const int m0   = blockIdx.y * 128;
    const int n0   = blockIdx.x * 128;
    const int gm   = wm * 32;
    const int gn   = wn * 64;
    const int row4 = lane >> 2;
    const int kq   = lane & 3;

    // loader assignments (4 x 16B per thread for A and for B)
    const float* asrc[4];
    const float* bsrc[4];
    uint32_t adst[4], bdst[4];
#pragma unroll
    for (int i = 0; i < 4; i++) {
        int v  = tid + 256 * i;
        int ar = v >> 3, ak = v & 7;       // A: 128 rows x 8 x 16B
        int br = v >> 5, bn = v & 31;      // B: 32 rows x 32 x 16B
        asrc[i] = A + (size_t)(m0 + ar) * EMB_ + ak * 4;
        bsrc[i] = W + (size_t)br * EMB_ + n0 + bn * 4;
        adst[i] = sbase + (uint32_t)(ar * 36 + ak * 4) * 4;
        bdst[i] = sbase + (uint32_t)(GSM_BS0 + br * 132 + bn * 4) * 4;
    }

    auto issue = [&](int c, int buf) {
        const size_t ka = (size_t)c * 32;
        const uint32_t ao = buf ? GSM_AS1 * 4 : 0;
        const uint32_t bo = buf ? (GSM_BS1 - GSM_BS0) * 4 : 0;
#pragma unroll
        for (int i = 0; i < 4; i++) {
            cpasync16(adst[i] + ao, asrc[i] + ka);
            cpasync16(bdst[i] + bo, bsrc[i] + ka * EMB_);
        }
        asm volatile("cp.async.commit_group;" ::: "memory");
    };

    float acc[2][8][4];
#pragma unroll
    for (int mt = 0; mt < 2; mt++)
#pragma unroll
        for (int nt = 0; nt < 8; nt++)
#pragma unroll
            for (int i = 0; i < 4; i++) acc[mt][nt][i] = 0.f;

    issue(0, 0);
    issue(1, 1);

#pragma unroll 1
    for (int c = 0; c < 32; c++) {
        if (c == 31) asm volatile("cp.async.wait_group 0;" ::: "memory");
        else         asm volatile("cp.async.wait_group 1;" ::: "memory");
        __syncthreads();

        const uint32_t* as = gsm + ((c & 1) ? GSM_AS1 : 0);
        const uint32_t* bs = gsm + GSM_BS0 + ((c & 1) ? (GSM_BS1 - GSM_BS0) : 0);

#pragma unroll
        for (int s = 0; s < 4; s++) {
            const int kk = s * 8;
            uint32_t a[2][4];
#pragma unroll
            for (int mt = 0; mt < 2; mt++) {
                const uint32_t* r0p = as + (gm + mt * 16 + row4) * 36;
                const uint32_t* r1p = as + (gm + mt * 16 + row4 + 8) * 36;
                a[mt][0] = r0p[kk + kq];
                a[mt][1] = r1p[kk + kq];
                a[mt][2] = r0p[kk + kq + 4];
                a[mt][3] = r1p[kk + kq + 4];
            }
#pragma unroll
            for (int nt = 0; nt < 8; nt++) {
                uint32_t b0 = bs[(kk + kq) * 132 + gn + nt * 8 + row4];
                uint32_t b1 = bs[(kk + kq + 4) * 132 + gn + nt * 8 + row4];
                mma_tf32(acc[0][nt], a[0], b0, b1);
                mma_tf32(acc[1][nt], a[1], b0, b1);
            }
        }
        __syncthreads();
        if (c + 2 < 32) issue(c + 2, c & 1);
    }

    // epilogue
#pragma unroll
    for (int mt = 0; mt < 2; mt++) {
        int r0 = m0 + gm + mt * 16 + row4;
#pragma unroll
        for (int nt = 0; nt < 8; nt++) {
            int cc = n0 + gn + nt * 8 + 2 * kq;
            float s0 = acc[mt][nt][0] + bias[cc];
            float s1 = acc[mt][nt][1] + bias[cc + 1];
            float s2 = acc[mt][nt][2] + bias[cc];
            float s3 = acc[mt][nt][3] + bias[cc + 1];
            if (mode) {
                if (mode == 2) { s0 *= 0.125f; s1 *= 0.125f; s2 *= 0.125f; s3 *= 0.125f; }
                float2 v0, v1;
                v0.x = __uint_as_float(tf32r(s0));
                v0.y = __uint_as_float(tf32r(s1));
                v1.x = __uint_as_float(tf32r(s2));
                v1.y = __uint_as_float(tf32r(s3));
                int h = cc >> 6, d = cc & 63;
                int b0r = r0 >> 11, sq0 = r0 & 2047;
                int b1r = (r0 + 8) >> 11, sq1 = (r0 + 8) & 2047;
                *(float2*)(out + ((size_t)(b0r * H_ + h) * S_ + sq0) * DH_ + d) = v0;
                *(float2*)(out + ((size_t)(b1r * H_ + h) * S_ + sq1) * DH_ + d) = v1;
            } else {
                float2 v0, v1;
                v0.x = s0; v0.y = s1;
                v1.x = s2; v1.y = s3;
                *(float2*)(out + (size_t)r0 * EMB_ + cc) = v0;
                *(float2*)(out + (size_t)(r0 + 8) * EMB_ + cc) = v1;
            }
        }
    }
}

__global__ __launch_bounds__(256) void qkv_mma_kernel(
    const float* __restrict__ bq, const float* __restrict__ bk,
    const float* __restrict__ bv)
{
    const int z = blockIdx.z;
    const float* W    = g_Wr + (size_t)z * (EMB_ * EMB_);
    const float* bias = (z == 0) ? bq : (z == 1) ? bk : bv;
    float* out        = (z == 0) ? g_Q : (z == 1) ? g_K : g_V;
    gemm_mma_body(g_xr, W, bias, out, (z == 0) ? 2 : 1);
}

__global__ __launch_bounds__(256) void oproj_mma_kernel(
    const float* __restrict__ bo, float* __restrict__ out)
{
    gemm_mma_body(g_ctx, g_Wr + (size_t)3 * (EMB_ * EMB_), bo, out, 0);
}

// ---------------------------------------------------------------------------
// Flash attention with tf32 mma.sync, v3:
//  * all inputs pre-rounded (and Q pre-scaled) by qkv epilogue -> loaders are
//    raw bit copies, zero cvt in the main loop
//  * Q/K pair-interleaved in k per 8-chunk -> conflict-free LDS.64 fragments
//  * ctx written tf32-rounded for the oproj cp.async pipeline
// CTA: 128 queries x one head, 16 iterations over 128-key tiles.
// Dynamic smem (u32): QS[128][72], KS[128][72], VS[128][68], PS[128][132],
//                     RED[512]
// ---------------------------------------------------------------------------
#define O_QS  0
#define O_KS  9216
#define O_VS  18432
#define O_PS  27136
#define O_RED 44032
#define ATTN_SMEM_U32 44544
#define ATTN_SMEM_BYTES (ATTN_SMEM_U32 * 4)

__global__ __launch_bounds__(256, 1) void attn_mma_kernel()
{
    extern __shared__ uint32_t sm[];
    float* smf = (float*)sm;

    const int tid  = threadIdx.x;
    const int lane = tid & 31;
    const int wid  = tid >> 5;
    const int wm   = wid & 3;
    const int wn   = wid >> 2;
    const int row4 = lane >> 2;
    const int kq   = lane & 3;
    const int gm   = wm * 32;
    const int gn   = wn * 64;     // S: key columns
    const int gn2  = wn * 32;     // PV: d columns

    const int bh = blockIdx.y;
    const int q0 = blockIdx.x * 128;

    const float* Qg = g_Q + ((size_t)bh * S_ + q0) * DH_;
    const float* Kg = g_K + (size_t)bh * S_ * DH_;
    const float* Vg = g_V + (size_t)bh * S_ * DH_;

    // ---- load Q tile: raw bits, pair-interleave k ----
#pragma unroll
    for (int i = 0; i < 4; i++) {
        int v   = tid + 256 * i;      // 0..1023
        int row = v >> 3;             // 0..127
        int seg = v & 7;              // 8-k segment
        const uint4* p = (const uint4*)(Qg + row * DH_ + seg * 8);
        uint4 a = p[0], b = p[1];
        uint4 u0, u1;
        u0.x = a.x; u0.y = b.x; u0.z = a.y; u0.w = b.y;
        u1.x = a.z; u1.y = b.z; u1.z = a.w; u1.w = b.w;
        *(uint4*)&sm[O_QS + row * 72 + seg * 8]     = u0;
        *(uint4*)&sm[O_QS + row * 72 + seg * 8 + 4] = u1;
    }

    float Oa[2][4][4];
#pragma unroll
    for (int mt = 0; mt < 2; mt++)
#pragma unroll
        for (int nt = 0; nt < 4; nt++)
#pragma unroll
            for (int i = 0; i < 4; i++) Oa[mt][nt][i] = 0.f;
    float m_run[2][2] = {{-1e30f, -1e30f}, {-1e30f, -1e30f}};
    float l_run[2][2] = {{0.f, 0.f}, {0.f, 0.f}};

#pragma unroll 1
    for (int kt = 0; kt < S_ / 128; kt++) {
        __syncthreads();   // previous iteration's mma reads of KS/VS/PS done
        const int k0 = kt * 128;
        // K: raw bits, pair-interleaved
#pragma unroll
        for (int i = 0; i < 4; i++) {
            int v   = tid + 256 * i;
            int row = v >> 3;
            int seg = v & 7;
            const uint4* p = (const uint4*)(Kg + (size_t)(k0 + row) * DH_ + seg * 8);
            uint4 a = p[0], b = p[1];
            uint4 u0, u1;
            u0.x = a.x; u0.y = b.x; u0.z = a.y; u0.w = b.y;
            u1.x = a.z; u1.y = b.z; u1.z = a.w; u1.w = b.w;
            *(uint4*)&sm[O_KS + row * 72 + seg * 8]     = u0;
            *(uint4*)&sm[O_KS + row * 72 + seg * 8 + 4] = u1;
        }
        // V: raw bit copy [key][d]
#pragma unroll
        for (int i = 0; i < 8; i++) {
            int v   = tid + 256 * i;
            int row = v >> 4;
            int c4  = v & 15;
            uint4 uv = *(const uint4*)(Vg + (size_t)(k0 + row) * DH_ + c4 * 4);
            *(uint4*)&sm[O_VS + row * 68 + c4 * 4] = uv;
        }
        __syncthreads();

        // ---- S = Q K^T (paired LDS.64 fragments) ----
        float acc[2][8][4];
#pragma unroll
        for (int mt = 0; mt < 2; mt++)
#pragma unroll
            for (int nt = 0; nt < 8; nt++)
#pragma unroll
                for (int i = 0; i < 4; i++) acc[mt][nt][i] = 0.f;

#pragma unroll
        for (int s = 0; s < 8; s++) {
            const int sc = s * 8 + 2 * kq;
            uint32_t a[2][4];
#pragma unroll
            for (int mt = 0; mt < 2; mt++) {
                uint2 qa = *(uint2*)&sm[O_QS + (gm + mt * 16 + row4) * 72 + sc];
                uint2 qb = *(uint2*)&sm[O_QS + (gm + mt * 16 + row4 + 8) * 72 + sc];
                a[mt][0] = qa.x; a[mt][1] = qb.x;
                a[mt][2] = qa.y; a[mt][3] = qb.y;
            }
#pragma unroll
            for (int nt = 0; nt < 8; nt++) {
                uint2 kb = *(uint2*)&sm[O_KS + (gn + nt * 8 + row4) * 72 + sc];
                mma_tf32(acc[0][nt], a[0], kb.x, kb.y);
                mma_tf32(acc[1][nt], a[1], kb.x, kb.y);
            }
        }

        // ---- online softmax ----
        float rmax[2][2];
#pragma unroll
        for (int mt = 0; mt < 2; mt++) {
            rmax[mt][0] = acc[mt][0][0];
            rmax[mt][1] = acc[mt][0][2];
#pragma unroll
            for (int nt = 0; nt < 8; nt++) {
                rmax[mt][0] = fmaxf(rmax[mt][0], fmaxf(acc[mt][nt][0], acc[mt][nt][1]));
                rmax[mt][1] = fmaxf(rmax[mt][1], fmaxf(acc[mt][nt][2], acc[mt][nt][3]));
            }
#pragma unroll
            for (int h = 0; h < 2; h++) {
                rmax[mt][h] = fmaxf(rmax[mt][h], __shfl_xor_sync(0xffffffffu, rmax[mt][h], 1));
                rmax[mt][h] = fmaxf(rmax[mt][h], __shfl_xor_sync(0xffffffffu, rmax[mt][h], 2));
            }
        }
        if (kq == 0) {
#pragma unroll
            for (int mt = 0; mt < 2; mt++)
#pragma unroll
                for (int h = 0; h < 2; h++)
                    smf[O_RED + wn * 128 + gm + mt * 16 + h * 8 + row4] = rmax[mt][h];
        }
        __syncthreads();

        float scale[2][2];
#pragma unroll
        for (int mt = 0; mt < 2; mt++)
#pragma unroll
            for (int h = 0; h < 2; h++) {
                int r = gm + mt * 16 + h * 8 + row4;
                float mtile = fmaxf(smf[O_RED + r], smf[O_RED + 128 + r]);
                float mnew  = fmaxf(m_run[mt][h], mtile);
                scale[mt][h] = __expf(m_run[mt][h] - mnew);
                m_run[mt][h] = mnew;
            }

        // p = exp(s - m), tf32 P -> smem, accumulate row sums
        float rsum[2][2] = {{0.f, 0.f}, {0.f, 0.f}};
#pragma unroll
        for (int mt = 0; mt < 2; mt++)
#pragma unroll
            for (int nt = 0; nt < 8; nt++) {
                float p0 = __expf(acc[mt][nt][0] - m_run[mt][0]);
                float p1 = __expf(acc[mt][nt][1] - m_run[mt][0]);
                float p2 = __expf(acc[mt][nt][2] - m_run[mt][1]);
                float p3 = __expf(acc[mt][nt][3] - m_run[mt][1]);
                rsum[mt][0] += p0 + p1;
                rsum[mt][1] += p2 + p3;
                int cc = gn + nt * 8 + 2 * kq;
                uint2 u0; u0.x = tf32r(p0); u0.y = tf32r(p1);
                uint2 u1; u1.x = tf32r(p2); u1.y = tf32r(p3);
                *(uint2*)&sm[O_PS + (gm + mt * 16 + row4) * 132 + cc] = u0;
                *(uint2*)&sm[O_PS + (gm + mt * 16 + row4 + 8) * 132 + cc] = u1;
            }
#pragma unroll
        for (int mt = 0; mt < 2; mt++)
#pragma unroll
            for (int h = 0; h < 2; h++) {
                rsum[mt][h] += __shfl_xor_sync(0xffffffffu, rsum[mt][h], 1);
                rsum[mt][h] += __shfl_xor_sync(0xffffffffu, rsum[mt][h], 2);
            }
        if (kq == 0) {
#pragma unroll
            for (int mt = 0; mt < 2; mt++)
#pragma unroll
                for (int h = 0; h < 2; h++)
                    smf[O_RED + 256 + wn * 128 + gm + mt * 16 + h * 8 + row4] = rsum[mt][h];
        }

        // rescale O while sums land
#pragma unroll
        for (int mt = 0; mt < 2; mt++)
#pragma unroll
            for (int nt = 0; nt < 4; nt++) {
                Oa[mt][nt][0] *= scale[mt][0];
                Oa[mt][nt][1] *= scale[mt][0];
                Oa[mt][nt][2] *= scale[mt][1];
                Oa[mt][nt][3] *= scale[mt][1];
            }
        __syncthreads();   // P + redsum visible

#pragma unroll
        for (int mt = 0; mt < 2; mt++)
#pragma unroll
            for (int h = 0; h < 2; h++) {
                int r = gm + mt * 16 + h * 8 + row4;
                l_run[mt][h] = l_run[mt][h] * scale[mt][h]
                             + smf[O_RED + 256 + r] + smf[O_RED + 256 + 128 + r];
            }

        // ---- O += P V ----
#pragma unroll
        for (int s2 = 0; s2 < 16; s2++) {
            const int kk = s2 * 8;
            uint32_t a[2][4];
#pragma unroll
            for (int mt = 0; mt < 2; mt++) {
                int rbase = (gm + mt * 16 + row4) * 132;
                a[mt][0] = sm[O_PS + rbase + kk + kq];
                a[mt][1] = sm[O_PS + rbase + 8 * 132 + kk + kq];
                a[mt][2] = sm[O_PS + rbase + kk + kq + 4];
                a[mt][3] = sm[O_PS + rbase + 8 * 132 + kk + kq + 4];
            }
#pragma unroll
            for (int nt = 0; nt < 4; nt++) {
                int nb = (kk + kq) * 68 + gn2 + nt * 8 + row4;
                uint32_t b0 = sm[O_VS + nb];
                uint32_t b1 = sm[O_VS + nb + 4 * 68];
                mma_tf32(Oa[0][nt], a[0], b0, b1);
                mma_tf32(Oa[1][nt], a[1], b0, b1);
            }
        }
    }

    // ---- epilogue: normalize, tf32-round, write ctx [B,S,EMB] ----
    const int b = bh >> 4;
    const int h = bh & 15;
#pragma unroll
    for (int mt = 0; mt < 2; mt++) {
        float inv0 = 1.f / l_run[mt][0];
        float inv1 = 1.f / l_run[mt][1];
        int r0 = q0 + gm + mt * 16 + row4;
#pragma unroll
        for (int nt = 0; nt < 4; nt++) {
            int d = gn2 + nt * 8 + 2 * kq;
            float2 v0, v1;
            v0.x = __uint_as_float(tf32r(Oa[mt][nt][0] * inv0));
            v0.y = __uint_as_float(tf32r(Oa[mt][nt][1] * inv0));
            v1.x = __uint_as_float(tf32r(Oa[mt][nt][2] * inv1));
            v1.y = __uint_as_float(tf32r(Oa[mt][nt][3] * inv1));
            *(float2*)(g_ctx + ((size_t)(b * S_) + r0) * EMB_ + h * DH_ + d) = v0;
            *(float2*)(g_ctx + ((size_t)(b * S_) + r0 + 8) * EMB_ + h * DH_ + d) = v1;
        }
    }
}

// ---------------------------------------------------------------------------
// Launch
// ---------------------------------------------------------------------------
extern "C" void kernel_launch(void* const* d_in, const int* in_sizes, int n_in,
                              void* d_out, int out_size)
{
    const float* x  = (const float*)d_in[0];
    const float* Wq = (const float*)d_in[1];
    const float* bq = (const float*)d_in[2];
    const float* Wk = (const float*)d_in[3];
    const float* bk = (const float*)d_in[4];
    const float* Wv = (const float*)d_in[5];
    const float* bv = (const float*)d_in[6];
    const float* Wo = (const float*)d_in[7];
    const float* bo = (const float*)d_in[8];
    float* out = (float*)d_out;

    cudaFuncSetAttribute(qkv_mma_kernel,
                         cudaFuncAttributeMaxDynamicSharedMemorySize, GSM_BYTES);
    cudaFuncSetAttribute(oproj_mma_kernel,
                         cudaFuncAttributeMaxDynamicSharedMemorySize, GSM_BYTES);
    cudaFuncSetAttribute(attn_mma_kernel,
                         cudaFuncAttributeMaxDynamicSharedMemorySize, ATTN_SMEM_BYTES);

    // prep: tf32-round x and all W (3,145,728 float4 total)
    round_prep_kernel<<<12288, 256>>>(x, Wq, Wk, Wv, Wo);

    dim3 gQKV(EMB_ / 128, M_ / 128, 3);           // (8, 64, 3)
    qkv_mma_kernel<<<gQKV, 256, GSM_BYTES>>>(bq, bk, bv);

    dim3 gAttn(S_ / 128, B_ * H_);                // (16, 64)
    attn_mma_kernel<<<gAttn, 256, ATTN_SMEM_BYTES>>>();

    dim3 gO(EMB_ / 128, M_ / 128);                // (8, 64)
    oproj_mma_kernel<<<gO, 256, GSM_BYTES>>>(bo, out);
}

// round 14
// speedup vs baseline: 1.0018x; 1.0018x over previous
#include <cuda_runtime.h>
#include <cstdint>

// Problem constants
#define B_   4
#define S_   2048
#define EMB_ 1024
#define H_   16
#define DH_  64
#define M_   (B_ * S_)          // 8192 rows

// Scratch (module-static device memory; no cudaMalloc anywhere)
__device__ float g_Q[B_ * H_ * S_ * DH_];   // [bh][s][d]  tf32-rounded, pre-scaled 1/8
__device__ float g_K[B_ * H_ * S_ * DH_];   // tf32-rounded
__device__ float g_V[B_ * H_ * S_ * DH_];   // tf32-rounded
__device__ float g_ctx[M_ * EMB_];          // [b*s][emb] tf32-rounded
__device__ float g_xr[M_ * EMB_];           // tf32-rounded x
__device__ float g_Wr[4 * EMB_ * EMB_];     // tf32-rounded Wq,Wk,Wv,Wo

// ---------------------------------------------------------------------------
// Helpers
// ---------------------------------------------------------------------------
__device__ __forceinline__ uint32_t tf32r(float f) {
    uint32_t u;
    asm("cvt.rna.tf32.f32 %0, %1;" : "=r"(u) : "f"(f));
    return u;
}

__device__ __forceinline__ void mma_tf32(float* c, const uint32_t* a,
                                         uint32_t b0, uint32_t b1) {
    asm volatile(
        "mma.sync.aligned.m16n8k8.row.col.f32.tf32.tf32.f32 "
        "{%0,%1,%2,%3}, {%4,%5,%6,%7}, {%8,%9}, {%0,%1,%2,%3};"
        : "+f"(c[0]), "+f"(c[1]), "+f"(c[2]), "+f"(c[3])
        : "r"(a[0]), "r"(a[1]), "r"(a[2]), "r"(a[3]), "r"(b0), "r"(b1));
}

// ---------------------------------------------------------------------------
// Prep kernel: round x and the four weight matrices to tf32 once.
// ---------------------------------------------------------------------------
__global__ __launch_bounds__(256) void round_prep_kernel(
    const float* __restrict__ x,
    const float* __restrict__ Wq, const float* __restrict__ Wk,
    const float* __restrict__ Wv, const float* __restrict__ Wo)
{
    size_t i = (size_t)blockIdx.x * 256 + threadIdx.x;   // float4 index
    const float4* src;
    uint4* dst;
    size_t off;
    if (i < 2097152) {                                   // x: 8M floats
        src = (const float4*)x;
        dst = (uint4*)g_xr;
        off = i;
    } else {
        size_t j = i - 2097152;
        int t = (int)(j >> 18);                          // 262144 float4 per W
        off = j & 262143;
        const float* w = (t == 0) ? Wq : (t == 1) ? Wk : (t == 2) ? Wv : Wo;
        src = (const float4*)w;
        dst = (uint4*)(g_Wr + (size_t)t * (EMB_ * EMB_));
    }
    float4 v = src[off];
    uint4 u;
    u.x = tf32r(v.x); u.y = tf32r(v.y); u.z = tf32r(v.z); u.w = tf32r(v.w);
    dst[off] = u;
}

// ---------------------------------------------------------------------------
// tf32 mma.sync GEMM (R10 register-prefetch structure, pre-rounded inputs):
// out[m,n] = sum_k A[m,k] * W[k,n] + bias[n]
// CTA tile 128x128, BK=32, 256 threads = 8 warps (4m x 2n), warp tile 32x64.
// mode: 0 = row-major fp32 out (oproj), 1 = scatter+round (K/V),
//       2 = scatter+*0.125+round (Q)
// ---------------------------------------------------------------------------
__device__ __forceinline__ void gemm_mma_body(
    const float* __restrict__ A, const float* __restrict__ W,
    const float* __restrict__ bias, float* __restrict__ out, int mode)
{
    __shared__ uint32_t As[128][36];   // [m][k]
    __shared__ uint32_t Bs[32][132];   // [k][n]

    const int tid  = threadIdx.x;
    const int lane = tid & 31;
    const int wid  = tid >> 5;
    const int wm   = wid & 3;
    const int wn   = wid >> 2;
    const int m0   = blockIdx.y * 128;
    const int n0   = blockIdx.x * 128;
    const int gm   = wm * 32;
    const int gn   = wn * 64;
    const int row4 = lane >> 2;
    const int kq   = lane & 3;

    float acc[2][8][4];
#pragma unroll
    for (int mt = 0; mt < 2; mt++)
#pragma unroll
        for (int nt = 0; nt < 8; nt++)
#pragma unroll
            for (int i = 0; i < 4; i++) acc[mt][nt][i] = 0.f;

    size_t aoff[4], boff[4];
    uint32_t* sA[4];
    uint32_t* sB[4];
#pragma unroll
    for (int i = 0; i < 4; i++) {
        int v = tid + 256 * i;
        int ar = v >> 3, ak = v & 7;
        int br = v >> 5, bn = v & 31;
        aoff[i] = (size_t)(m0 + ar) * EMB_ + ak * 4;
        boff[i] = (size_t)br * EMB_ + n0 + bn * 4;
        sA[i] = &As[ar][ak * 4];
        sB[i] = &Bs[br][bn * 4];
    }

    uint4 pa[4], pb[4];
#pragma unroll
    for (int i = 0; i < 4; i++) {
        pa[i] = *(const uint4*)(A + aoff[i]);
        pb[i] = *(const uint4*)(W + boff[i]);
    }

#pragma unroll 1
    for (int c = 0; c < 32; c++) {
        if (c > 0) __syncthreads();
#pragma unroll
        for (int i = 0; i < 4; i++) {
            *(uint4*)sA[i] = pa[i];
            *(uint4*)sB[i] = pb[i];
        }
        __syncthreads();

        if (c < 31) {
            size_t ka = (size_t)(c + 1) * 32;
#pragma unroll
            for (int i = 0; i < 4; i++) {
                pa[i] = *(const uint4*)(A + aoff[i] + ka);
                pb[i] = *(const uint4*)(W + boff[i] + ka * EMB_);
            }
        }

#pragma unroll
        for (int s = 0; s < 4; s++) {
            const int kk = s * 8;
            uint32_t a[2][4];
#pragma unroll
            for (int mt = 0; mt < 2; mt++) {
                a[mt][0] = As[gm + mt * 16 + row4][kk + kq];
                a[mt][1] = As[gm + mt * 16 + row4 + 8][kk + kq];
                a[mt][2] = As[gm + mt * 16 + row4][kk + kq + 4];
                a[mt][3] = As[gm + mt * 16 + row4 + 8][kk + kq + 4];
            }
#pragma unroll
            for (int nt = 0; nt < 8; nt++) {
                uint32_t b0 = Bs[kk + kq][gn + nt * 8 + row4];
                uint32_t b1 = Bs[kk + kq + 4][gn + nt * 8 + row4];
                mma_tf32(acc[0][nt], a[0], b0, b1);
                mma_tf32(acc[1][nt], a[1], b0, b1);
            }
        }
    }

#pragma unroll
    for (int mt = 0; mt < 2; mt++) {
        int r0 = m0 + gm + mt * 16 + row4;
#pragma unroll
        for (int nt = 0; nt < 8; nt++) {
            int cc = n0 + gn + nt * 8 + 2 * kq;
            float s0 = acc[mt][nt][0] + bias[cc];
            float s1 = acc[mt][nt][1] + bias[cc + 1];
            float s2 = acc[mt][nt][2] + bias[cc];
            float s3 = acc[mt][nt][3] + bias[cc + 1];
            if (mode) {
                if (mode == 2) { s0 *= 0.125f; s1 *= 0.125f; s2 *= 0.125f; s3 *= 0.125f; }
                float2 v0, v1;
                v0.x = __uint_as_float(tf32r(s0));
                v0.y = __uint_as_float(tf32r(s1));
                v1.x = __uint_as_float(tf32r(s2));
                v1.y = __uint_as_float(tf32r(s3));
                int h = cc >> 6, d = cc & 63;
                int b0r = r0 >> 11, sq0 = r0 & 2047;
                int b1r = (r0 + 8) >> 11, sq1 = (r0 + 8) & 2047;
                *(float2*)(out + ((size_t)(b0r * H_ + h) * S_ + sq0) * DH_ + d) = v0;
                *(float2*)(out + ((size_t)(b1r * H_ + h) * S_ + sq1) * DH_ + d) = v1;
            } else {
                float2 v0, v1;
                v0.x = s0; v0.y = s1;
                v1.x = s2; v1.y = s3;
                *(float2*)(out + (size_t)r0 * EMB_ + cc) = v0;
                *(float2*)(out + (size_t)(r0 + 8) * EMB_ + cc) = v1;
            }
        }
    }
}

__global__ __launch_bounds__(256, 2) void qkv_mma_kernel(
    const float* __restrict__ bq, const float* __restrict__ bk,
    const float* __restrict__ bv)
{
    const int z = blockIdx.z;
    const float* W    = g_Wr + (size_t)z * (EMB_ * EMB_);
    const float* bias = (z == 0) ? bq : (z == 1) ? bk : bv;
    float* out        = (z == 0) ? g_Q : (z == 1) ? g_K : g_V;
    gemm_mma_body(g_xr, W, bias, out, (z == 0) ? 2 : 1);
}

__global__ __launch_bounds__(256, 2) void oproj_mma_kernel(
    const float* __restrict__ bo, float* __restrict__ out)
{
    gemm_mma_body(g_ctx, g_Wr + (size_t)3 * (EMB_ * EMB_), bo, out, 0);
}

// ---------------------------------------------------------------------------
// Flash attention v4: register-resident P via warp shuffles, 64-query CTA,
// ~91KB smem -> 2 CTAs/SM.
// 8 warps: wm = wid&3 (16 q rows each), wn = wid>>2 (key half 0/1).
// S: warp tile 16q x 64k.  PV: each wn computes PARTIAL O (16q x 64d) over its
// 64 keys; partials merged once at epilogue (same global-max sequence).
// A-fragments for PV built from S-accumulator by 4-lane shuffle permutation.
// Smem (u32): QS[64][72], KS[128][72] (k pair-interleaved), VS[128][72] plain,
//             RED[128], LB[64].  Obuf reuses KS.
// ---------------------------------------------------------------------------
#define O_QS  0
#define O_KS  4608
#define O_VS  13824
#define O_RED 23040
#define O_LB  23168
#define ATTN_SMEM_U32 23232
#define ATTN_SMEM_BYTES (ATTN_SMEM_U32 * 4)

__global__ __launch_bounds__(256, 2) void attn_mma_kernel()
{
    extern __shared__ uint32_t sm[];
    float* smf = (float*)sm;

    const int tid  = threadIdx.x;
    const int lane = tid & 31;
    const int wid  = tid >> 5;
    const int wm   = wid & 3;
    const int wn   = wid >> 2;
    const int row4 = lane >> 2;
    const int kq   = lane & 3;
    const int gm   = wm * 16;       // query rows (16 per warp)
    const int gn   = wn * 64;       // key half

    const int bh = blockIdx.y;
    const int q0 = blockIdx.x * 64;

    const float* Qg = g_Q + ((size_t)bh * S_ + q0) * DH_;
    const float* Kg = g_K + (size_t)bh * S_ * DH_;
    const float* Vg = g_V + (size_t)bh * S_ * DH_;

    // shuffle sources for P fragment construction (constant per thread)
    const int src1 = (lane & ~3) | (kq >> 1);
    const int src2 = src1 + 2;
    const bool oddq = (kq & 1);

    // ---- load Q tile: raw bits, pair-interleave k (stride 72) ----
#pragma unroll
    for (int i = 0; i < 2; i++) {
        int v   = tid + 256 * i;      // 0..511
        int row = v >> 3;             // 0..63
        int seg = v & 7;
        const uint4* p = (const uint4*)(Qg + row * DH_ + seg * 8);
        uint4 a = p[0], b = p[1];
        uint4 u0, u1;
        u0.x = a.x; u0.y = b.x; u0.z = a.y; u0.w = b.y;
        u1.x = a.z; u1.y = b.z; u1.z = a.w; u1.w = b.w;
        *(uint4*)&sm[O_QS + row * 72 + seg * 8]     = u0;
        *(uint4*)&sm[O_QS + row * 72 + seg * 8 + 4] = u1;
    }

    float Oa[8][4];                  // partial O: 16q x 64d (8 d-tiles)
#pragma unroll
    for (int nt = 0; nt < 8; nt++)
#pragma unroll
        for (int i = 0; i < 4; i++) Oa[nt][i] = 0.f;
    float m_run[2] = {-1e30f, -1e30f};
    float l_run[2] = {0.f, 0.f};     // PARTIAL over this wn's keys

#pragma unroll 1
    for (int kt = 0; kt < S_ / 128; kt++) {
        __syncthreads();   // previous tile's KS/VS reads done
        const int k0 = kt * 128;
        // K: pair-interleaved, stride 72
#pragma unroll
        for (int i = 0; i < 4; i++) {
            int v   = tid + 256 * i;
            int row = v >> 3;         // 0..127
            int seg = v & 7;
            const uint4* p = (const uint4*)(Kg + (size_t)(k0 + row) * DH_ + seg * 8);
            uint4 a = p[0], b = p[1];
            uint4 u0, u1;
            u0.x = a.x; u0.y = b.x; u0.z = a.y; u0.w = b.y;
            u1.x = a.z; u1.y = b.z; u1.z = a.w; u1.w = b.w;
            *(uint4*)&sm[O_KS + row * 72 + seg * 8]     = u0;
            *(uint4*)&sm[O_KS + row * 72 + seg * 8 + 4] = u1;
        }
        // V: plain [key][d], stride 72
#pragma unroll
        for (int i = 0; i < 8; i++) {
            int v   = tid + 256 * i;
            int row = v >> 4;         // 0..127
            int c4  = v & 15;
            uint4 uv = *(const uint4*)(Vg + (size_t)(k0 + row) * DH_ + c4 * 4);
            *(uint4*)&sm[O_VS + row * 72 + c4 * 4] = uv;
        }
        __syncthreads();

        // ---- S = Q K^T over this wn's 64 keys ----
        float acc[8][4];
#pragma unroll
        for (int nt = 0; nt < 8; nt++)
#pragma unroll
            for (int i = 0; i < 4; i++) acc[nt][i] = 0.f;

#pragma unroll
        for (int s = 0; s < 8; s++) {
            const int sc = s * 8 + 2 * kq;
            uint2 qa = *(uint2*)&sm[O_QS + (gm + row4) * 72 + sc];
            uint2 qb = *(uint2*)&sm[O_QS + (gm + row4 + 8) * 72 + sc];
            uint32_t a[4];
            a[0] = qa.x; a[1] = qb.x; a[2] = qa.y; a[3] = qb.y;
#pragma unroll
            for (int nt = 0; nt < 8; nt++) {
                uint2 kb = *(uint2*)&sm[O_KS + (gn + nt * 8 + row4) * 72 + sc];
                mma_tf32(acc[nt], a, kb.x, kb.y);
            }
        }

        // ---- online softmax (max global across wn; sums stay partial) ----
        float rmax[2];
        rmax[0] = acc[0][0];
        rmax[1] = acc[0][2];
#pragma unroll
        for (int nt = 0; nt < 8; nt++) {
            rmax[0] = fmaxf(rmax[0], fmaxf(acc[nt][0], acc[nt][1]));
            rmax[1] = fmaxf(rmax[1], fmaxf(acc[nt][2], acc[nt][3]));
        }
#pragma unroll
        for (int h = 0; h < 2; h++) {
            rmax[h] = fmaxf(rmax[h], __shfl_xor_sync(0xffffffffu, rmax[h], 1));
            rmax[h] = fmaxf(rmax[h], __shfl_xor_sync(0xffffffffu, rmax[h], 2));
        }
        if (kq == 0) {
            smf[O_RED + wn * 64 + gm + row4]     = rmax[0];
            smf[O_RED + wn * 64 + gm + 8 + row4] = rmax[1];
        }
        __syncthreads();

        float scale[2];
#pragma unroll
        for (int h = 0; h < 2; h++) {
            int r = gm + h * 8 + row4;
            float mtile = fmaxf(smf[O_RED + r], smf[O_RED + 64 + r]);
            float mnew  = fmaxf(m_run[h], mtile);
            scale[h] = __expf(m_run[h] - mnew);
            m_run[h] = mnew;
        }

        // p = exp(s - m) in place; partial row sums; then tf32-round p
#pragma unroll
        for (int nt = 0; nt < 8; nt++) {
            acc[nt][0] = __expf(acc[nt][0] - m_run[0]);
            acc[nt][1] = __expf(acc[nt][1] - m_run[0]);
            acc[nt][2] = __expf(acc[nt][2] - m_run[1]);
            acc[nt][3] = __expf(acc[nt][3] - m_run[1]);
        }
        float rsum[2] = {0.f, 0.f};
#pragma unroll
        for (int nt = 0; nt < 8; nt++) {
            rsum[0] += acc[nt][0] + acc[nt][1];
            rsum[1] += acc[nt][2] + acc[nt][3];
        }
#pragma unroll
        for (int h = 0; h < 2; h++) {
            rsum[h] += __shfl_xor_sync(0xffffffffu, rsum[h], 1);
            rsum[h] += __shfl_xor_sync(0xffffffffu, rsum[h], 2);
            l_run[h] = l_run[h] * scale[h] + rsum[h];
        }
#pragma unroll
        for (int nt = 0; nt < 8; nt++) {
            acc[nt][0] = __uint_as_float(tf32r(acc[nt][0]));
            acc[nt][1] = __uint_as_float(tf32r(acc[nt][1]));
            acc[nt][2] = __uint_as_float(tf32r(acc[nt][2]));
            acc[nt][3] = __uint_as_float(tf32r(acc[nt][3]));
        }

        // rescale partial O
#pragma unroll
        for (int nt = 0; nt < 8; nt++) {
            Oa[nt][0] *= scale[0];
            Oa[nt][1] *= scale[0];
            Oa[nt][2] *= scale[1];
            Oa[nt][3] *= scale[1];
        }

        // ---- O += P V over this wn's 64 keys (P via shuffle) ----
#pragma unroll
        for (int ink = 0; ink < 8; ink++) {
            float s1p0 = __shfl_sync(0xffffffffu, acc[ink][0], src1);
            float s1p1 = __shfl_sync(0xffffffffu, acc[ink][1], src1);
            float s1p2 = __shfl_sync(0xffffffffu, acc[ink][2], src1);
            float s1p3 = __shfl_sync(0xffffffffu, acc[ink][3], src1);
            float s2p0 = __shfl_sync(0xffffffffu, acc[ink][0], src2);
            float s2p1 = __shfl_sync(0xffffffffu, acc[ink][1], src2);
            float s2p2 = __shfl_sync(0xffffffffu, acc[ink][2], src2);
            float s2p3 = __shfl_sync(0xffffffffu, acc[ink][3], src2);
            uint32_t a[4];
            a[0] = __float_as_uint(oddq ? s1p1 : s1p0);
            a[1] = __float_as_uint(oddq ? s1p3 : s1p2);
            a[2] = __float_as_uint(oddq ? s2p1 : s2p0);
            a[3] = __float_as_uint(oddq ? s2p3 : s2p2);
            const int kr0 = (gn + ink * 8 + kq) * 72;
            const int kr1 = (gn + ink * 8 + kq + 4) * 72;
#pragma unroll
            for (int nt = 0; nt < 8; nt++) {
                uint32_t b0 = sm[O_VS + kr0 + nt * 8 + row4];
                uint32_t b1 = sm[O_VS + kr1 + nt * 8 + row4];
                mma_tf32(Oa[nt], a, b0, b1);
            }
        }
    }

    // ---- merge wn partials, normalize, tf32-round, write ctx ----
    __syncthreads();   // all PV reads of KS done; safe to reuse as Obuf
    if (wn == 1) {
#pragma unroll
        for (int nt = 0; nt < 8; nt++) {
            int d = nt * 8 + 2 * kq;
            float2 v0, v1;
            v0.x = Oa[nt][0]; v0.y = Oa[nt][1];
            v1.x = Oa[nt][2]; v1.y = Oa[nt][3];
            *(float2*)&smf[O_KS + (gm + row4) * 72 + d]     = v0;
            *(float2*)&smf[O_KS + (gm + 8 + row4) * 72 + d] = v1;
        }
        if (kq == 0) {
            smf[O_LB + gm + row4]     = l_run[0];
            smf[O_LB + gm + 8 + row4] = l_run[1];
        }
    }
    __syncthreads();
    if (wn == 0) {
        const int b = bh >> 4;
        const int h = bh & 15;
        int r0 = gm + row4;
        int r1 = gm + 8 + row4;
        float inv0 = 1.f / (l_run[0] + smf[O_LB + r0]);
        float inv1 = 1.f / (l_run[1] + smf[O_LB + r1]);
        float* o0 = g_ctx + ((size_t)(b * S_) + q0 + r0) * EMB_ + h * DH_;
        float* o1 = g_ctx + ((size_t)(b * S_) + q0 + r1) * EMB_ + h * DH_;
#pragma unroll
        for (int nt = 0; nt < 8; nt++) {
            int d = nt * 8 + 2 * kq;
            float2 p0 = *(float2*)&smf[O_KS + r0 * 72 + d];
            float2 p1 = *(float2*)&smf[O_KS + r1 * 72 + d];
            float2 v0, v1;
            v0.x = __uint_as_float(tf32r((Oa[nt][0] + p0.x) * inv0));
            v0.y = __uint_as_float(tf32r((Oa[nt][1] + p0.y) * inv0));
            v1.x = __uint_as_float(tf32r((Oa[nt][2] + p1.x) * inv1));
            v1.y = __uint_as_float(tf32r((Oa[nt][3] + p1.y) * inv1));
            *(float2*)(o0 + d) = v0;
            *(float2*)(o1 + d) = v1;
        }
    }
}

// ---------------------------------------------------------------------------
// Launch
// ---------------------------------------------------------------------------
extern "C" void kernel_launch(void* const* d_in, const int* in_sizes, int n_in,
                              void* d_out, int out_size)
{
    const float* x  = (const float*)d_in[0];
    const float* Wq = (const float*)d_in[1];
    const float* bq = (const float*)d_in[2];
    const float* Wk = (const float*)d_in[3];
    const float* bk = (const float*)d_in[4];
    const float* Wv = (const float*)d_in[5];
    const float* bv = (const float*)d_in[6];
    const float* Wo = (const float*)d_in[7];
    const float* bo = (const float*)d_in[8];
    float* out = (float*)d_out;

    cudaFuncSetAttribute(attn_mma_kernel,
                         cudaFuncAttributeMaxDynamicSharedMemorySize, ATTN_SMEM_BYTES);

    // prep: tf32-round x and all W (3,145,728 float4 total)
    round_prep_kernel<<<12288, 256>>>(x, Wq, Wk, Wv, Wo);

    dim3 gQKV(EMB_ / 128, M_ / 128, 3);           // (8, 64, 3)
    qkv_mma_kernel<<<gQKV, 256>>>(bq, bk, bv);

    dim3 gAttn(S_ / 64, B_ * H_);                 // (32, 64)
    attn_mma_kernel<<<gAttn, 256, ATTN_SMEM_BYTES>>>();

    dim3 gO(EMB_ / 128, M_ / 128);                // (8, 64)
    oproj_mma_kernel<<<gO, 256>>>(bo, out);
}